// round 10
// baseline (speedup 1.0000x reference)
#include <cuda_runtime.h>
#include <math.h>
#include <stdint.h>

#define BATCH 4
#define SEQ   1024
#define DM    1024
#define NH    16
#define DH    64

// Scratch (device globals — no allocation allowed)
__device__ float g_q[(size_t)BATCH*NH*SEQ*DH];   // [b*NH+h][s][d]
__device__ float g_k[(size_t)BATCH*SEQ*DH];      // [b*S+s][d]
__device__ float g_v[(size_t)BATCH*SEQ*DH];
__device__ float g_ctx[(size_t)BATCH*SEQ*DM];    // [b*S+s][h*DH+d]

// ---------------------------------------------------------------------------
// TF32 helpers
// ---------------------------------------------------------------------------
__device__ __forceinline__ float f2tf(float x) {
    uint32_t u;
    asm("cvt.rna.tf32.f32 %0, %1;" : "=r"(u) : "f"(x));
    return __uint_as_float(u);
}

__device__ __forceinline__ void mma_tf32(float* c, const uint32_t* a, const uint32_t* b) {
    asm volatile(
        "mma.sync.aligned.m16n8k8.row.col.f32.tf32.tf32.f32 "
        "{%0,%1,%2,%3}, {%4,%5,%6,%7}, {%8,%9}, {%0,%1,%2,%3};\n"
        : "+f"(c[0]), "+f"(c[1]), "+f"(c[2]), "+f"(c[3])
        : "r"(a[0]), "r"(a[1]), "r"(a[2]), "r"(a[3]), "r"(b[0]), "r"(b[1]));
}

// ---------------------------------------------------------------------------
// TF32 GEMM, double-buffered smem (1 barrier per k-iter). (R8, unchanged)
// MODE 2: out = A @ Wo^T + bias
// MODE 4: fused projections: x<8 -> q permuted; x==8 -> k,v.
// ---------------------------------------------------------------------------
#define GP 20

template<int MODE>
__global__ __launch_bounds__(256, 2)
void gemm_tf32(const float* __restrict__ A, const float* __restrict__ B,
               const float* __restrict__ Bk, const float* __restrict__ Bv,
               const float* __restrict__ bias,
               float* __restrict__ C, float* __restrict__ Ck, float* __restrict__ Cv,
               int M, int N, int K)
{
    __shared__ float sA[2][128 * GP];
    __shared__ float sB[2][128 * GP];

    const int tid  = threadIdx.x;
    const int lane = tid & 31;
    const int w    = tid >> 5;
    const int wr   = w >> 1;
    const int wc   = w & 1;
    const int g    = lane >> 2;
    const int t    = lane & 3;
    const int m0   = blockIdx.y * 128;
    const bool kv  = (MODE == 4) && (blockIdx.x == 8);
    const int n0   = kv ? 0 : blockIdx.x * 128;

    const int ldr = tid >> 2;
    const int ldc = (tid & 3) * 4;

    float acc[2][8][4];
    #pragma unroll
    for (int mt = 0; mt < 2; mt++)
        #pragma unroll
        for (int nt = 0; nt < 8; nt++)
            #pragma unroll
            for (int q = 0; q < 4; q++) acc[mt][nt][q] = 0.f;

    float4 ar[2], br[2];

    #pragma unroll
    for (int h = 0; h < 2; h++) {
        const int row = ldr + h * 64;
        ar[h] = *(const float4*)&A[(size_t)(m0 + row) * K + ldc];
        if (MODE == 4 && kv) {
            const float* Bs = (row >= 64) ? Bv : Bk;
            br[h] = *(const float4*)&Bs[(size_t)(row & 63) * K + ldc];
        } else {
            br[h] = *(const float4*)&B[(size_t)(n0 + row) * K + ldc];
        }
    }
    {
        #pragma unroll
        for (int h = 0; h < 2; h++) {
            const int row = ldr + h * 64;
            float* da = &sA[0][row * GP + ldc];
            da[0] = f2tf(ar[h].x); da[1] = f2tf(ar[h].y);
            da[2] = f2tf(ar[h].z); da[3] = f2tf(ar[h].w);
            float* db = &sB[0][row * GP + ldc];
            db[0] = f2tf(br[h].x); db[1] = f2tf(br[h].y);
            db[2] = f2tf(br[h].z); db[3] = f2tf(br[h].w);
        }
        #pragma unroll
        for (int h = 0; h < 2; h++) {
            const int row = ldr + h * 64;
            ar[h] = *(const float4*)&A[(size_t)(m0 + row) * K + 16 + ldc];
            if (MODE == 4 && kv) {
                const float* Bs = (row >= 64) ? Bv : Bk;
                br[h] = *(const float4*)&Bs[(size_t)(row & 63) * K + 16 + ldc];
            } else {
                br[h] = *(const float4*)&B[(size_t)(n0 + row) * K + 16 + ldc];
            }
        }
    }
    __syncthreads();

    const int nIt = K >> 4;
    for (int it = 0; it < nIt; it++) {
        const int buf = it & 1;
        const float* cA = sA[buf];
        const float* cB = sB[buf];

        #pragma unroll
        for (int ks = 0; ks < 2; ks++) {
            const int k = ks * 8;
            uint32_t af[2][4], bf[8][2];
            #pragma unroll
            for (int mt = 0; mt < 2; mt++) {
                const int mr = wr * 32 + mt * 16;
                af[mt][0] = __float_as_uint(cA[(mr + g) * GP + k + t]);
                af[mt][1] = __float_as_uint(cA[(mr + g + 8) * GP + k + t]);
                af[mt][2] = __float_as_uint(cA[(mr + g) * GP + k + t + 4]);
                af[mt][3] = __float_as_uint(cA[(mr + g + 8) * GP + k + t + 4]);
            }
            #pragma unroll
            for (int nt = 0; nt < 8; nt++) {
                const int nn = wc * 64 + nt * 8 + g;
                bf[nt][0] = __float_as_uint(cB[nn * GP + k + t]);
                bf[nt][1] = __float_as_uint(cB[nn * GP + k + t + 4]);
            }
            #pragma unroll
            for (int mt = 0; mt < 2; mt++)
                #pragma unroll
                for (int nt = 0; nt < 8; nt++)
                    mma_tf32(acc[mt][nt], af[mt], bf[nt]);
        }

        if (it + 1 < nIt) {
            float* dA = sA[buf ^ 1];
            float* dB = sB[buf ^ 1];
            #pragma unroll
            for (int h = 0; h < 2; h++) {
                const int row = ldr + h * 64;
                float* da = &dA[row * GP + ldc];
                da[0] = f2tf(ar[h].x); da[1] = f2tf(ar[h].y);
                da[2] = f2tf(ar[h].z); da[3] = f2tf(ar[h].w);
                float* db = &dB[row * GP + ldc];
                db[0] = f2tf(br[h].x); db[1] = f2tf(br[h].y);
                db[2] = f2tf(br[h].z); db[3] = f2tf(br[h].w);
            }
            if (it + 2 < nIt) {
                const int k0 = (it + 2) * 16;
                #pragma unroll
                for (int h = 0; h < 2; h++) {
                    const int row = ldr + h * 64;
                    ar[h] = *(const float4*)&A[(size_t)(m0 + row) * K + k0 + ldc];
                    if (MODE == 4 && kv) {
                        const float* Bs = (row >= 64) ? Bv : Bk;
                        br[h] = *(const float4*)&Bs[(size_t)(row & 63) * K + k0 + ldc];
                    } else {
                        br[h] = *(const float4*)&B[(size_t)(n0 + row) * K + k0 + ldc];
                    }
                }
            }
        }
        __syncthreads();
    }

    #pragma unroll
    for (int mt = 0; mt < 2; mt++) {
        #pragma unroll
        for (int rr = 0; rr < 2; rr++) {
            const int m = m0 + wr * 32 + mt * 16 + g + rr * 8;
            #pragma unroll
            for (int nt = 0; nt < 8; nt++) {
                const int n = n0 + wc * 64 + nt * 8 + 2 * t;
                const float v0 = acc[mt][nt][rr * 2 + 0];
                const float v1 = acc[mt][nt][rr * 2 + 1];
                if (MODE == 2) {
                    *(float2*)&C[(size_t)m * N + n] =
                        make_float2(v0 + bias[n], v1 + bias[n + 1]);
                } else if (MODE == 4 && !kv) {
                    const int b = m >> 10, s = m & 1023;
                    const int h = n >> 6, d = n & 63;
                    *(float2*)&C[(((size_t)(b * NH + h)) * SEQ + s) * DH + d] =
                        make_float2(v0, v1);
                } else {
                    float* dst = wc ? Cv : Ck;
                    const int nn = nt * 8 + 2 * t;
                    *(float2*)&dst[(size_t)m * 64 + nn] = make_float2(v0, v1);
                }
            }
        }
    }
}

// ---------------------------------------------------------------------------
// Fused attention v2: split c2c/c2p, 2 queries per CTA, 512 threads.
// 16 warps = (i-group ig, batch b, half). K and V tiles are loaded RAW once
// per tile and shared by both i-groups; scores = Q@K^T + Q@rel[i]^T via two
// accumulating MMA passes. Softmax/AV identical per group.
// ---------------------------------------------------------------------------
#define AP 68   // pitch for sQ / sK / sRel / sP
#define VP 72   // pitch for V rows (72 % 32 == 8 -> AV B-frag conflict-free)

#define SM_Q    (2 * 64 * AP)          // [ig][row 64][AP]
#define SM_KVB  (4 * 64 * VP)          // K (pitch AP) / V (pitch VP), shared
#define SM_REL  (2 * 64 * AP)          // [ig][j][AP]+d
#define SM_P    (2 * 64 * AP)          // [ig][row][AP]
#define SM_ATTN_FLOATS (SM_Q + SM_KVB + SM_REL + SM_P + 2 * 256)
#define SM_ATTN_BYTES  (SM_ATTN_FLOATS * 4)

__global__ __launch_bounds__(512, 1)
void attn_kernel(const float* __restrict__ rel,
                 const float* __restrict__ qb,
                 const float* __restrict__ kb,
                 const float* __restrict__ vb,
                 float* __restrict__ ctx)
{
    extern __shared__ float sm[];
    float* sQ   = sm;                    // [ig][64][AP] (pre-scaled by 1/8)
    float* sKV  = sQ + SM_Q;             // K raw pitch AP / V tf32 pitch VP
    float* sRel = sKV + SM_KVB;          // [ig][64][AP]
    float* sP   = sRel + SM_REL;         // [ig][64][AP]
    float* sExM = sP + SM_P;             // [16 warps][16 rows]
    float* sExS = sExM + 256;            // [16 warps][16 rows]

    const int tid   = threadIdx.x;
    const int lane  = tid & 31;
    const int w     = tid >> 5;          // 0..15
    const int ig    = w >> 3;            // i-group 0/1
    const int b     = (w >> 1) & 3;      // batch
    const int half  = w & 1;             // j-half (scores) / d-half (AV)
    const int g     = lane >> 2;
    const int t     = lane & 3;
    const int t256  = tid & 255;         // group-local thread id
    const int i     = blockIdx.x * 2 + ig;
    const int iQ    = blockIdx.x * 2 + (tid >> 8);  // for cooperative Q load
    const unsigned FULL = 0xffffffffu;

    float* sQg = sQ + ig * (64 * AP);
    float* sRg = sRel + ig * (64 * AP);
    float* sPg = sP + ig * (64 * AP);

    // Load Q for both queries (each 256-thread group loads its own), 1/8 scale
    #pragma unroll
    for (int tix = 0; tix < 16; tix++) {
        const int idx = tix * 256 + t256;
        const int r = idx >> 6, d = idx & 63;
        sQ[(tid >> 8) * (64 * AP) + r * AP + d] =
            0.125f * qb[((size_t)r * SEQ + iQ) * DH + d];
    }

    // prologue: each group prefetches its tile-0 rel into registers
    float4 relbuf[4];
    #pragma unroll
    for (int tix = 0; tix < 4; tix++) {
        const int idx = tix * 256 + t256;
        const int j  = idx >> 4;
        const int d4 = (idx & 15) * 4;
        relbuf[tix] = *(const float4*)&rel[((size_t)i * SEQ + j) * DH + d4];
    }

    // per-warp running softmax state for rows b*16+g, b*16+g+8 of query i
    float mr0 = -INFINITY, mr1 = -INFINITY, lr0 = 0.f, lr1 = 0.f;
    float cacc[4][4];
    #pragma unroll
    for (int nt = 0; nt < 4; nt++)
        #pragma unroll
        for (int q = 0; q < 4; q++) cacc[nt][q] = 0.f;

    for (int j0 = 0; j0 < SEQ; j0 += 64) {
        __syncthreads();   // S0: prev tile's AV reads (sKV, sP) complete

        // ---- store K raw (all 512 threads, shared tile, pitch AP) ----
        #pragma unroll
        for (int tix = 0; tix < 2; tix++) {
            const int idx = tix * 512 + tid;      // 1024 quads: 4b x 64j x 4 dq
            const int bb = idx >> 8;
            const int j  = (idx >> 2) & 63;
            const int d4 = (idx & 3) * 16;        // 0,16,32,48
            #pragma unroll
            for (int s = 0; s < 4; s++) {
                *(float4*)&sKV[(bb * 64 + j) * AP + d4 + 4 * s] = // wait, wrong
                    *(const float4*)&kb[((size_t)(bb * SEQ) + j0 + j) * DH + d4 + 4 * s];
            }
        }
        // ---- store this group's rel tile from prefetched registers ----
        #pragma unroll
        for (int tix = 0; tix < 4; tix++) {
            const int idx = tix * 256 + t256;
            const int j  = idx >> 4;
            const int d4 = (idx & 15) * 4;
            *(float4*)&sRg[j * AP + d4] = relbuf[tix];
        }
        __syncthreads();   // S1

        // ---- prefetch next tile's rel ----
        if (j0 + 64 < SEQ) {
            #pragma unroll
            for (int tix = 0; tix < 4; tix++) {
                const int idx = tix * 256 + t256;
                const int j  = idx >> 4;
                const int d4 = (idx & 15) * 4;
                relbuf[tix] =
                    *(const float4*)&rel[((size_t)i * SEQ + j0 + 64 + j) * DH + d4];
            }
        }

        // ---- scores: pr = Q@K^T + Q@rel^T (both accumulate) ----
        float pr[4][4];
        #pragma unroll
        for (int nt = 0; nt < 4; nt++)
            #pragma unroll
            for (int q = 0; q < 4; q++) pr[nt][q] = 0.f;

        #pragma unroll
        for (int ks = 0; ks < 8; ks++) {
            const int k = ks * 8;
            uint32_t af[4], bf[2];
            af[0] = __float_as_uint(sQg[(b * 16 + g) * AP + k + t]);
            af[1] = __float_as_uint(sQg[(b * 16 + g + 8) * AP + k + t]);
            af[2] = __float_as_uint(sQg[(b * 16 + g) * AP + k + t + 4]);
            af[3] = __float_as_uint(sQg[(b * 16 + g + 8) * AP + k + t + 4]);
            #pragma unroll
            for (int nt = 0; nt < 4; nt++) {
                const int n = half * 32 + nt * 8 + g;
                bf[0] = __float_as_uint(sKV[(b * 64 + n) * AP + k + t]);
                bf[1] = __float_as_uint(sKV[(b * 64 + n) * AP + k + t + 4]);
                mma_tf32(pr[nt], af, bf);
            }
            #pragma unroll
            for (int nt = 0; nt < 4; nt++) {
                const int n = half * 32 + nt * 8 + g;
                bf[0] = __float_as_uint(sRg[n * AP + k + t]);
                bf[1] = __float_as_uint(sRg[n * AP + k + t + 4]);
                mma_tf32(pr[nt], af, bf);
            }
        }

        // ---- row max (quad reduce) + cross-half exchange ----
        float m0 = -INFINITY, m1 = -INFINITY;
        #pragma unroll
        for (int nt = 0; nt < 4; nt++) {
            m0 = fmaxf(m0, fmaxf(pr[nt][0], pr[nt][1]));
            m1 = fmaxf(m1, fmaxf(pr[nt][2], pr[nt][3]));
        }
        m0 = fmaxf(m0, __shfl_xor_sync(FULL, m0, 1));
        m0 = fmaxf(m0, __shfl_xor_sync(FULL, m0, 2));
        m1 = fmaxf(m1, __shfl_xor_sync(FULL, m1, 1));
        m1 = fmaxf(m1, __shfl_xor_sync(FULL, m1, 2));
        if (t == 0) {
            sExM[w * 16 + g]     = m0;
            sExM[w * 16 + 8 + g] = m1;
        }
        __syncthreads();   // S2: sExM ready; all K reads done -> V may overwrite

        const float pm0 = sExM[(w ^ 1) * 16 + g];
        const float pm1 = sExM[(w ^ 1) * 16 + 8 + g];
        const float mn0 = fmaxf(mr0, fmaxf(m0, pm0));
        const float mn1 = fmaxf(mr1, fmaxf(m1, pm1));
        const float corr0 = __expf(mr0 - mn0);
        const float corr1 = __expf(mr1 - mn1);
        mr0 = mn0; mr1 = mn1;

        // ---- exp in registers, single tf32 P write, row sums ----
        float s0 = 0.f, s1 = 0.f;
        #pragma unroll
        for (int nt = 0; nt < 4; nt++) {
            float p0 = __expf(pr[nt][0] - mn0);
            float p1 = __expf(pr[nt][1] - mn0);
            float p2 = __expf(pr[nt][2] - mn1);
            float p3 = __expf(pr[nt][3] - mn1);
            s0 += p0 + p1; s1 += p2 + p3;
            const int jc = half * 32 + nt * 8 + 2 * t;
            *(float2*)&sPg[(b * 16 + g) * AP + jc] =
                make_float2(f2tf(p0), f2tf(p1));
            *(float2*)&sPg[(b * 16 + g + 8) * AP + jc] =
                make_float2(f2tf(p2), f2tf(p3));
        }
        s0 += __shfl_xor_sync(FULL, s0, 1);
        s0 += __shfl_xor_sync(FULL, s0, 2);
        s1 += __shfl_xor_sync(FULL, s1, 1);
        s1 += __shfl_xor_sync(FULL, s1, 2);
        if (t == 0) {
            sExS[w * 16 + g]     = s0;
            sExS[w * 16 + 8 + g] = s1;
        }

        // ---- V: gmem [b][j][d] -> sKV rows pitch VP (rna tf32, shared) ----
        #pragma unroll
        for (int tix = 0; tix < 2; tix++) {
            const int idx = tix * 512 + tid;
            const int bb = idx >> 8;
            const int j  = (idx >> 2) & 63;
            const int d4 = (idx & 3) * 16;
            #pragma unroll
            for (int s = 0; s < 4; s++) {
                const float4 v4 =
                    *(const float4*)&vb[((size_t)(bb * SEQ) + j0 + j) * DH + d4 + 4 * s];
                float4 o;
                o.x = f2tf(v4.x); o.y = f2tf(v4.y);
                o.z = f2tf(v4.z); o.w = f2tf(v4.w);
                *(float4*)&sKV[(bb * 64 + j) * VP + d4 + 4 * s] = o;
            }
        }
        __syncthreads();   // S3: sP, sKV(V), sExS ready

        lr0 = lr0 * corr0 + s0 + sExS[(w ^ 1) * 16 + g];
        lr1 = lr1 * corr1 + s1 + sExS[(w ^ 1) * 16 + 8 + g];

        // ---- rescale ctx + AV MMA: N=32 d (half), K=64 j ----
        #pragma unroll
        for (int nt = 0; nt < 4; nt++) {
            cacc[nt][0] *= corr0; cacc[nt][1] *= corr0;
            cacc[nt][2] *= corr1; cacc[nt][3] *= corr1;
        }
        #pragma unroll
        for (int ks = 0; ks < 8; ks++) {
            const int k = ks * 8;   // j within tile
            uint32_t af[4], bf[2];
            af[0] = __float_as_uint(sPg[(b * 16 + g) * AP + k + t]);
            af[1] = __float_as_uint(sPg[(b * 16 + g + 8) * AP + k + t]);
            af[2] = __float_as_uint(sPg[(b * 16 + g) * AP + k + t + 4]);
            af[3] = __float_as_uint(sPg[(b * 16 + g + 8) * AP + k + t + 4]);
            #pragma unroll
            for (int nt = 0; nt < 4; nt++) {
                const int n = half * 32 + nt * 8 + g;   // d column
                bf[0] = __float_as_uint(sKV[(b * 64 + k + t) * VP + n]);
                bf[1] = __float_as_uint(sKV[(b * 64 + k + t + 4) * VP + n]);
                mma_tf32(cacc[nt], af, bf);
            }
        }
    }

    // ---- epilogue: normalize + write ctx [b][i][h*DH + d] ----
    {
        const float inv0 = 1.f / lr0;
        const float inv1 = 1.f / lr1;
        const size_t base = ((size_t)(b * SEQ) + i) * DM;
        #pragma unroll
        for (int nt = 0; nt < 4; nt++) {
            const int d = half * 32 + nt * 8 + 2 * t;
            *(float2*)&ctx[base + g * DH + d] =
                make_float2(cacc[nt][0] * inv0, cacc[nt][1] * inv0);
            *(float2*)&ctx[base + (g + 8) * DH + d] =
                make_float2(cacc[nt][2] * inv1, cacc[nt][3] * inv1);
        }
    }
}

// ---------------------------------------------------------------------------
extern "C" void kernel_launch(void* const* d_in, const int* in_sizes, int n_in,
                              void* d_out, int out_size)
{
    const float* x   = (const float*)d_in[0];
    const float* rel = (const float*)d_in[1];
    const float* Wq  = (const float*)d_in[2];
    const float* Wk  = (const float*)d_in[3];
    const float* Wv  = (const float*)d_in[4];
    const float* Wo  = (const float*)d_in[5];
    const float* bo  = (const float*)d_in[6];
    float* out = (float*)d_out;

    float *qb, *kb, *vb, *ctx;
    cudaGetSymbolAddress((void**)&qb,  g_q);
    cudaGetSymbolAddress((void**)&kb,  g_k);
    cudaGetSymbolAddress((void**)&vb,  g_v);
    cudaGetSymbolAddress((void**)&ctx, g_ctx);

    cudaFuncSetAttribute(attn_kernel,
                         cudaFuncAttributeMaxDynamicSharedMemorySize,
                         SM_ATTN_BYTES);

    const int M = BATCH * SEQ;  // 4096

    // fused q|k|v projections: blocks x=0..7 -> q (permuted), x=8 -> k,v
    {
        dim3 grid(9, M / 128);
        gemm_tf32<4><<<grid, 256>>>(x, Wq, Wk, Wv, nullptr,
                                    qb, kb, vb, M, DM, DM);
    }
    // fused attention: 2 queries per CTA
    attn_kernel<<<SEQ / 2, 512, SM_ATTN_BYTES>>>(rel, qb, kb, vb, ctx);

    // out = ctx @ Wo^T + bo
    {
        dim3 grid(8, M / 128);
        gemm_tf32<2><<<grid, 256>>>(ctx, Wo, nullptr, nullptr, bo,
                                    out, nullptr, nullptr, M, DM, DM);
    }
}